// round 10
// baseline (speedup 1.0000x reference)
#include <cuda_runtime.h>
#include <cuda_bf16.h>
#include <math.h>
#include <stdint.h>

// Problem constants
#define HID   1024
#define NTOK  4096          // B*S
#define KDIM  9216          // 1024 silu + 8192 spline bases
#define K2    18432         // stored: [hi | lo]
#define OUT3  3072
#define SEQ   2048
#define BHN   32
#define DH    64

// GEMM tiling (CTA 256x128, K-chunk 64, 3-stage)
#define BM 256
#define BN 128
#define BK 64
#define A_STG 32768
#define B_STG 16384
#define STG_BYTES (A_STG + B_STG)
#define SM_B_OFF A_STG
#define NSTG 3

// ---------------- scratch (static __device__, no allocations) ----------------
__device__ __align__(16) __nv_bfloat16 g_Abf[(long)NTOK * K2];   // 151 MB
__device__ __align__(16) __nv_bfloat16 g_Bbf[(long)OUT3 * K2];   // 113 MB
__device__ __align__(16) float g_qkv [(long)NTOK * OUT3];
__device__ __align__(16) __nv_bfloat16 g_qbf[(long)BHN * 2 * SEQ * DH];
__device__ __align__(16) __nv_bfloat16 g_kbf[(long)BHN * 2 * SEQ * DH];
__device__ __align__(16) __nv_bfloat16 g_vt [(long)BHN * 2 * DH * SEQ];
__device__ __align__(16) __nv_bfloat16 g_ctxbf[(long)NTOK * 2 * HID];  // [hi|lo]
__device__ __align__(16) __nv_bfloat16 g_owbf [(long)HID * 2 * HID];   // [hi|lo]

__device__ __forceinline__ uint32_t smem_u32(const void* p) {
    uint32_t a;
    asm("{ .reg .u64 t; cvta.to.shared.u64 t, %1; cvt.u32.u64 %0, t; }"
        : "=r"(a) : "l"(p));
    return a;
}
#define CP_ASYNC16(smaddr, gptr) \
    asm volatile("cp.async.cg.shared.global [%0], [%1], 16;" :: "r"(smaddr), "l"(gptr))
#define CP_COMMIT() asm volatile("cp.async.commit_group;")
#define CP_WAIT1()  asm volatile("cp.async.wait_group 1;")
#define CP_WAIT0()  asm volatile("cp.async.wait_group 0;")
#define LDSM_X4(r0,r1,r2,r3,addr) \
    asm volatile("ldmatrix.sync.aligned.m8n8.x4.shared.b16 {%0,%1,%2,%3}, [%4];" \
        : "=r"(r0),"=r"(r1),"=r"(r2),"=r"(r3) : "r"(addr))
#define HMMA(d, a, b0v, b1v) \
    asm volatile("mma.sync.aligned.m16n8k16.row.col.f32.bf16.bf16.f32 " \
        "{%0,%1,%2,%3}, {%4,%5,%6,%7}, {%8,%9}, {%0,%1,%2,%3};" \
        : "+f"(d[0]),"+f"(d[1]),"+f"(d[2]),"+f"(d[3]) \
        : "r"(a[0]),"r"(a[1]),"r"(a[2]),"r"(a[3]), "r"(b0v),"r"(b1v))

__device__ __forceinline__ uint32_t pk2(float a, float b) {
    __nv_bfloat162 t = __floats2bfloat162_rn(a, b);
    return *(uint32_t*)&t;
}

// ---------------- prep: Bbf = [hi | lo] of [bw | sw*sc] ----------------------
__global__ void prep_w(const float* __restrict__ bw,
                       const float* __restrict__ sw,
                       const float* __restrict__ sc)
{
    long i = (long)blockIdx.x * 256 + threadIdx.x;
    if (i >= (long)OUT3 * HID) return;
    int in = (int)(i & 1023);
    float s = sc[i];
    long rb = (long)(i >> 10) * K2;
    float v = bw[i];
    __nv_bfloat16 h = __float2bfloat16_rn(v);
    __nv_bfloat16 l = __float2bfloat16_rn(v - __bfloat162float(h));
    g_Bbf[rb + in] = h;
    g_Bbf[rb + KDIM + in] = l;
    __nv_bfloat16 h8[8], l8[8];
#pragma unroll
    for (int j = 0; j < 8; j++) {
        float w = sw[i * 8 + j] * s;
        h8[j] = __float2bfloat16_rn(w);
        l8[j] = __float2bfloat16_rn(w - __bfloat162float(h8[j]));
    }
    long c = rb + HID + (long)in * 8;
    *(uint4*)&g_Bbf[c]        = *(uint4*)h8;
    *(uint4*)&g_Bbf[c + KDIM] = *(uint4*)l8;
}

// ---------------- prep: Abf = [hi | lo] of [silu(x) | b_splines(x)] ---------
__global__ void prep_a(const float* __restrict__ x,
                       const float* __restrict__ grid)
{
    long i = (long)blockIdx.x * 256 + threadIdx.x;
    if (i >= (long)NTOK * HID) return;
    int in = (int)(i & 1023);
    float xv = x[i];
    long ra = (long)(i >> 10) * K2;
    float sv = xv / (1.0f + expf(-xv));
    __nv_bfloat16 h = __float2bfloat16_rn(sv);
    __nv_bfloat16 l = __float2bfloat16_rn(sv - __bfloat162float(h));
    g_Abf[ra + in] = h;
    g_Abf[ra + KDIM + in] = l;
    float g[12];
#pragma unroll
    for (int t = 0; t < 12; t++) g[t] = grid[in * 12 + t];
    float bas[11];
#pragma unroll
    for (int j = 0; j < 11; j++)
        bas[j] = (xv >= g[j] && xv < g[j + 1]) ? 1.0f : 0.0f;
#pragma unroll
    for (int p = 1; p <= 3; p++) {
#pragma unroll
        for (int j = 0; j < 11 - p; j++) {
            bas[j] = (xv - g[j]) / (g[j + p] - g[j]) * bas[j]
                   + (g[j + p + 1] - xv) / (g[j + p + 1] - g[j + 1]) * bas[j + 1];
        }
    }
    __nv_bfloat16 h8[8], l8[8];
#pragma unroll
    for (int j = 0; j < 8; j++) {
        h8[j] = __float2bfloat16_rn(bas[j]);
        l8[j] = __float2bfloat16_rn(bas[j] - __bfloat162float(h8[j]));
    }
    long c = ra + HID + (long)in * 8;
    *(uint4*)&g_Abf[c]        = *(uint4*)h8;
    *(uint4*)&g_Abf[c + KDIM] = *(uint4*)l8;
}

// ---------------- prep: out_w -> [hi | lo] -----------------------------------
__global__ void prep_ow(const float* __restrict__ ow)
{
    long i = (long)blockIdx.x * 256 + threadIdx.x;
    if (i >= (long)HID * HID) return;
    int c = (int)(i & 1023);
    long rb = (long)(i >> 10) * (2 * HID);
    float v = ow[i];
    __nv_bfloat16 h = __float2bfloat16_rn(v);
    __nv_bfloat16 l = __float2bfloat16_rn(v - __bfloat162float(h));
    g_owbf[rb + c] = h;
    g_owbf[rb + HID + c] = l;
}

// ---------------- generic 3-term split HMMA GEMM -----------------------------
// C(MxN) = A * B^T over virtual K = 3*kdim (A: hi,lo,hi / B: hi,hi,lo).
// CTA 256x128x64; 3-stage cp.async; register-double-buffered fragments.
__global__ void __launch_bounds__(256, 1) gemm3_mma(
    const __nv_bfloat16* __restrict__ A, const __nv_bfloat16* __restrict__ B,
    float* __restrict__ C,
    int k2, int seg, int ntt, int ldc, const float* __restrict__ bias)
{
    extern __shared__ char smem[];
    const uint32_t sb = smem_u32(smem);
    const int tid = threadIdx.x;
    const int wid = tid >> 5;
    const int lane = tid & 31;
    const int m0 = blockIdx.y * BM;
    const int n0 = blockIdx.x * BN;
    const int wm = wid & 3;
    const int wn = wid >> 2;

    const int r0 = tid >> 3;
    const int c0 = tid & 7;
    const __nv_bfloat16* aG = A + (long)(m0 + r0) * k2 + c0 * 8;
    const __nv_bfloat16* bG = B + (long)(n0 + r0) * k2 + c0 * 8;
    uint32_t sA[8], sB[4];
#pragma unroll
    for (int u = 0; u < 8; u++) {
        int row = r0 + u * 32;
        sA[u] = sb + row * 128 + ((c0 ^ (row & 7)) << 4);
    }
#pragma unroll
    for (int u = 0; u < 4; u++) {
        int row = r0 + u * 32;
        sB[u] = sb + SM_B_OFF + row * 128 + ((c0 ^ (row & 7)) << 4);
    }

#pragma unroll
    for (int s = 0; s < 2; s++) {
        long co = (long)s * BK;
        uint32_t bo = s * STG_BYTES;
#pragma unroll
        for (int u = 0; u < 8; u++)
            CP_ASYNC16(sA[u] + bo, aG + (long)u * 32 * k2 + co);
#pragma unroll
        for (int u = 0; u < 4; u++)
            CP_ASYNC16(sB[u] + bo, bG + (long)u * 32 * k2 + co);
        CP_COMMIT();
    }

    float acc[4][8][4];
#pragma unroll
    for (int mi = 0; mi < 4; mi++)
#pragma unroll
        for (int ni = 0; ni < 8; ni++)
#pragma unroll
            for (int r = 0; r < 4; r++) acc[mi][ni][r] = 0.0f;

    const int lrow = lane & 15;
    const int lchk = lane >> 4;
    const int lswz = lane & 7;
    uint32_t aRow[4], bRow[4];
#pragma unroll
    for (int mi = 0; mi < 4; mi++)
        aRow[mi] = (uint32_t)((wm * 64 + mi * 16 + lrow) * 128);
#pragma unroll
    for (int bi = 0; bi < 4; bi++)
        bRow[bi] = (uint32_t)(SM_B_OFF + (wn * 64 + bi * 16 + lrow) * 128);

    uint32_t af[2][4][4], bf[2][4][4];

    for (int t = 0; t < ntt; t++) {
        CP_WAIT1();
        __syncthreads();
        const uint32_t stb = sb + (t % NSTG) * STG_BYTES;

        // preload kk=0 fragments (overlaps the cp.async issue below)
        {
            const uint32_t sw = (uint32_t)((lchk ^ lswz) << 4);
#pragma unroll
            for (int mi = 0; mi < 4; mi++)
                LDSM_X4(af[0][mi][0], af[0][mi][1], af[0][mi][2], af[0][mi][3],
                        stb + aRow[mi] + sw);
#pragma unroll
            for (int bi = 0; bi < 4; bi++)
                LDSM_X4(bf[0][bi][0], bf[0][bi][1], bf[0][bi][2], bf[0][bi][3],
                        stb + bRow[bi] + sw);
        }

        if (t + 2 < ntt) {
            int ch = t + 2;
            int chA = (ch < 2 * seg) ? ch : ch - 2 * seg;   // hi,lo,hi
            int chB = (ch < seg)     ? ch : ch - seg;       // hi,hi,lo
            long coA = (long)chA * BK;
            long coB = (long)chB * BK;
            uint32_t bo = ((t + 2) % NSTG) * STG_BYTES;
#pragma unroll
            for (int u = 0; u < 8; u++)
                CP_ASYNC16(sA[u] + bo, aG + (long)u * 32 * k2 + coA);
#pragma unroll
            for (int u = 0; u < 4; u++)
                CP_ASYNC16(sB[u] + bo, bG + (long)u * 32 * k2 + coB);
        }
        CP_COMMIT();

#pragma unroll
        for (int kk = 0; kk < 4; kk++) {
            const int cur = kk & 1, nxt = cur ^ 1;
            if (kk < 3) {
                const uint32_t sw =
                    (uint32_t)((((kk + 1) * 2 + lchk) ^ lswz) << 4);
#pragma unroll
                for (int mi = 0; mi < 4; mi++)
                    LDSM_X4(af[nxt][mi][0], af[nxt][mi][1],
                            af[nxt][mi][2], af[nxt][mi][3],
                            stb + aRow[mi] + sw);
#pragma unroll
                for (int bi = 0; bi < 4; bi++)
                    LDSM_X4(bf[nxt][bi][0], bf[nxt][bi][1],
                            bf[nxt][bi][2], bf[nxt][bi][3],
                            stb + bRow[bi] + sw);
            }
#pragma unroll
            for (int mi = 0; mi < 4; mi++)
#pragma unroll
                for (int bi = 0; bi < 4; bi++) {
                    HMMA(acc[mi][2*bi],   af[cur][mi], bf[cur][bi][0], bf[cur][bi][2]);
                    HMMA(acc[mi][2*bi+1], af[cur][mi], bf[cur][bi][1], bf[cur][bi][3]);
                }
        }
    }

    const int erow = lane >> 2;
    const int ecol = (lane & 3) * 2;
#pragma unroll
    for (int mi = 0; mi < 4; mi++) {
        long row = m0 + wm * 64 + mi * 16 + erow;
#pragma unroll
        for (int ni = 0; ni < 8; ni++) {
            int col = n0 + wn * 64 + ni * 8 + ecol;
            float v0 = acc[mi][ni][0], v1 = acc[mi][ni][1];
            float v2 = acc[mi][ni][2], v3 = acc[mi][ni][3];
            if (bias) {
                float b0 = bias[col], b1 = bias[col + 1];
                v0 += b0; v1 += b1; v2 += b0; v3 += b1;
            }
            *(float2*)&C[row * ldc + col] = make_float2(v0, v1);
            *(float2*)&C[(row + 8) * ldc + col] = make_float2(v2, v3);
        }
    }
}

// ---------------- rotate q,k by R; emit bf16 hi/lo planes + v^T -------------
__global__ void __launch_bounds__(256) rotqkv(const float* __restrict__ R)
{
    const int bh = blockIdx.x;
    const int s0 = blockIdx.y * 64;
    const int b = bh >> 4, h = bh & 15;
    __shared__ float RsT[64][65];
    __shared__ float T[64][65];
    __shared__ float Tv[64][65];
    const int tid = threadIdx.x;
    const long plane = (long)SEQ * DH;
    const long vplane = (long)DH * SEQ;

    for (int i = tid; i < 4096; i += 256) {
        int m = i >> 6, d = i & 63;
        RsT[d][m] = R[i];
    }
    for (int i = tid; i < 4096; i += 256) {
        int t = i >> 6, d = i & 63;
        long n = (long)(b * SEQ + s0 + t);
        const float* base = g_qkv + n * OUT3 + h * 192;
        T[t][d] = base[d];
        Tv[t][d] = base[128 + d];
    }
    __syncthreads();
    for (int i = tid; i < 4096; i += 256) {
        int t = i >> 6, m = i & 63;
        float sum = 0.0f;
#pragma unroll
        for (int d = 0; d < 64; d++) sum += T[t][d] * RsT[d][m];
        sum *= 0.125f;
        __nv_bfloat16 hi = __float2bfloat16_rn(sum);
        __nv_bfloat16 lo = __float2bfloat16_rn(sum - __bfloat162float(hi));
        long idx = ((long)(bh * 2) * SEQ + s0 + t) * DH + m;
        g_qbf[idx] = hi;
        g_qbf[idx + plane] = lo;
    }
    for (int i = tid; i < 4096; i += 256) {
        int d = i >> 6, t = i & 63;
        float v = Tv[t][d];
        __nv_bfloat16 hi = __float2bfloat16_rn(v);
        __nv_bfloat16 lo = __float2bfloat16_rn(v - __bfloat162float(hi));
        long idx = ((long)(bh * 2) * DH + d) * SEQ + s0 + t;
        g_vt[idx] = hi;
        g_vt[idx + vplane] = lo;
    }
    __syncthreads();
    for (int i = tid; i < 4096; i += 256) {
        int t = i >> 6, d = i & 63;
        long n = (long)(b * SEQ + s0 + t);
        T[t][d] = g_qkv[n * OUT3 + h * 192 + 64 + d];
    }
    __syncthreads();
    for (int i = tid; i < 4096; i += 256) {
        int t = i >> 6, m = i & 63;
        float sum = 0.0f;
#pragma unroll
        for (int d = 0; d < 64; d++) sum += T[t][d] * RsT[d][m];
        __nv_bfloat16 hi = __float2bfloat16_rn(sum);
        __nv_bfloat16 lo = __float2bfloat16_rn(sum - __bfloat162float(hi));
        long idx = ((long)(bh * 2) * SEQ + s0 + t) * DH + m;
        g_kbf[idx] = hi;
        g_kbf[idx + plane] = lo;
    }
}

// ---------------- HMMA flash attention; ctx out as bf16 hi/lo ---------------
#define FS_KV   16384
#define FS_BUF  32768
#define FS_TOT  (FS_KV + 2 * FS_BUF)
__global__ void __launch_bounds__(128, 1) flash_attn_mma()
{
    extern __shared__ char smem[];
    const uint32_t sb = smem_u32(smem);
    const int tid = threadIdx.x;
    const int wid = tid >> 5;
    const int lane = tid & 31;
    const int bh = blockIdx.y;
    const int q0 = blockIdx.x * 64;
    const int b = bh >> 4, h = bh & 15;

    const int lr = tid >> 3;
    const int lc = tid & 7;
    uint32_t soff[4];
#pragma unroll
    for (int u = 0; u < 4; u++) {
        int row = lr + u * 16;
        soff[u] = row * 128 + ((lc ^ (row & 7)) << 4);
    }
    const long qplane = (long)SEQ * DH;
    const long vplane = (long)DH * SEQ;

#pragma unroll
    for (int p = 0; p < 2; p++)
#pragma unroll
        for (int u = 0; u < 4; u++) {
            int row = lr + u * 16;
            const __nv_bfloat16* src =
                g_qbf + ((long)(bh * 2) * SEQ + q0 + row) * DH + p * qplane + lc * 8;
            CP_ASYNC16(sb + p * 8192 + soff[u], src);
        }
    {
        uint32_t bo = sb + FS_KV;
#pragma unroll
        for (int p = 0; p < 2; p++)
#pragma unroll
            for (int u = 0; u < 4; u++) {
                int row = lr + u * 16;
                const __nv_bfloat16* ks =
                    g_kbf + ((long)(bh * 2) * SEQ + row) * DH + p * qplane + lc * 8;
                CP_ASYNC16(bo + p * 8192 + soff[u], ks);
                const __nv_bfloat16* vs =
                    g_vt + ((long)(bh * 2) * DH + row) * SEQ + p * vplane + lc * 8;
                CP_ASYNC16(bo + 16384 + p * 8192 + soff[u], vs);
            }
    }
    CP_COMMIT();

    const int lrow = lane & 15;
    const int lchk = lane >> 4;
    const int lswz = lane & 7;
    const uint32_t aRow = (uint32_t)((wid * 16 + lrow) * 128);
    uint32_t bRow[4];
#pragma unroll
    for (int bi = 0; bi < 4; bi++)
        bRow[bi] = (uint32_t)((bi * 16 + lrow) * 128);

    float m0 = -1e30f, m1 = -1e30f, l0 = 0.f, l1 = 0.f;
    float o[8][4];
#pragma unroll
    for (int nt = 0; nt < 8; nt++)
#pragma unroll
        for (int r = 0; r < 4; r++) o[nt][r] = 0.0f;

    const int NKT = SEQ / 64;
    for (int t = 0; t < NKT; t++) {
        if (t + 1 < NKT) {
            uint32_t bo = sb + FS_KV + ((t + 1) & 1) * FS_BUF;
            int s0n = (t + 1) * 64;
#pragma unroll
            for (int p = 0; p < 2; p++)
#pragma unroll
                for (int u = 0; u < 4; u++) {
                    int row = lr + u * 16;
                    const __nv_bfloat16* ks =
                        g_kbf + ((long)(bh * 2) * SEQ + s0n + row) * DH + p * qplane + lc * 8;
                    CP_ASYNC16(bo + p * 8192 + soff[u], ks);
                    const __nv_bfloat16* vs =
                        g_vt + ((long)(bh * 2) * DH + row) * SEQ + p * vplane + s0n + lc * 8;
                    CP_ASYNC16(bo + 16384 + p * 8192 + soff[u], vs);
                }
            CP_COMMIT();
            CP_WAIT1();
        } else {
            CP_WAIT0();
        }
        __syncthreads();

        const uint32_t stb = sb + FS_KV + (t & 1) * FS_BUF;

        float s[8][4];
#pragma unroll
        for (int nt = 0; nt < 8; nt++)
#pragma unroll
            for (int r = 0; r < 4; r++) s[nt][r] = 0.0f;
#pragma unroll
        for (int kk = 0; kk < 4; kk++) {
            const uint32_t sw = (uint32_t)(((kk * 2 + lchk) ^ lswz) << 4);
            uint32_t ah[4], al[4];
            LDSM_X4(ah[0], ah[1], ah[2], ah[3], sb + aRow + sw);
            LDSM_X4(al[0], al[1], al[2], al[3], sb + 8192 + aRow + sw);
#pragma unroll
            for (int bi = 0; bi < 4; bi++) {
                uint32_t kh[4], kl[4];
                LDSM_X4(kh[0], kh[1], kh[2], kh[3], stb + bRow[bi] + sw);
                LDSM_X4(kl[0], kl[1], kl[2], kl[3], stb + 8192 + bRow[bi] + sw);
                HMMA(s[2*bi],   ah, kh[0], kh[2]);
                HMMA(s[2*bi+1], ah, kh[1], kh[3]);
                HMMA(s[2*bi],   al, kh[0], kh[2]);
                HMMA(s[2*bi+1], al, kh[1], kh[3]);
                HMMA(s[2*bi],   ah, kl[0], kl[2]);
                HMMA(s[2*bi+1], ah, kl[1], kl[3]);
            }
        }

        float tm0 = -1e30f, tm1 = -1e30f;
#pragma unroll
        for (int nt = 0; nt < 8; nt++) {
            tm0 = fmaxf(tm0, fmaxf(s[nt][0], s[nt][1]));
            tm1 = fmaxf(tm1, fmaxf(s[nt][2], s[nt][3]));
        }
        tm0 = fmaxf(tm0, __shfl_xor_sync(0xffffffffu, tm0, 1));
        tm0 = fmaxf(tm0, __shfl_xor_sync(0xffffffffu, tm0, 2));
        tm1 = fmaxf(tm1, __shfl_xor_sync(0xffffffffu, tm1, 1));
        tm1 = fmaxf(tm1, __shfl_xor_sync(0xffffffffu, tm1, 2));
        float nm0 = fmaxf(m0, tm0), nm1 = fmaxf(m1, tm1);
        float c0 = __expf(m0 - nm0), c1 = __expf(m1 - nm1);
        m0 = nm0; m1 = nm1;
        float p[8][4];
        float ts0 = 0.f, ts1 = 0.f;
#pragma unroll
        for (int nt = 0; nt < 8; nt++) {
            p[nt][0] = __expf(s[nt][0] - nm0);
            p[nt][1] = __expf(s[nt][1] - nm0);
            p[nt][2] = __expf(s[nt][2] - nm1);
            p[nt][3] = __expf(s[nt][3] - nm1);
            ts0 += p[nt][0] + p[nt][1];
            ts1 += p[nt][2] + p[nt][3];
        }
        ts0 += __shfl_xor_sync(0xffffffffu, ts0, 1);
        ts0 += __shfl_xor_sync(0xffffffffu, ts0, 2);
        ts1 += __shfl_xor_sync(0xffffffffu, ts1, 1);
        ts1 += __shfl_xor_sync(0xffffffffu, ts1, 2);
        l0 = l0 * c0 + ts0;
        l1 = l1 * c1 + ts1;
#pragma unroll
        for (int nt = 0; nt < 8; nt++) {
            o[nt][0] *= c0; o[nt][1] *= c0;
            o[nt][2] *= c1; o[nt][3] *= c1;
        }

#pragma unroll
        for (int kb = 0; kb < 4; kb++) {
            float h00 = p[2*kb][0], h01 = p[2*kb][1];
            float h02 = p[2*kb][2], h03 = p[2*kb][3];
            float h10 = p[2*kb+1][0], h11 = p[2*kb+1][1];
            float h12 = p[2*kb+1][2], h13 = p[2*kb+1][3];
            uint32_t phi[4], plo[4];
            phi[0] = pk2(h00, h01); phi[1] = pk2(h02, h03);
            phi[2] = pk2(h10, h11); phi[3] = pk2(h12, h13);
            __nv_bfloat162 t0 = *(__nv_bfloat162*)&phi[0];
            __nv_bfloat162 t1 = *(__nv_bfloat162*)&phi[1];
            __nv_bfloat162 t2 = *(__nv_bfloat162*)&phi[2];
            __nv_bfloat162 t3 = *(__nv_bfloat162*)&phi[3];
            plo[0] = pk2(h00 - __bfloat162float(t0.x), h01 - __bfloat162float(t0.y));
            plo[1] = pk2(h02 - __bfloat162float(t1.x), h03 - __bfloat162float(t1.y));
            plo[2] = pk2(h10 - __bfloat162float(t2.x), h11 - __bfloat162float(t2.y));
            plo[3] = pk2(h12 - __bfloat162float(t3.x), h13 - __bfloat162float(t3.y));

            const uint32_t sw = (uint32_t)(((kb * 2 + lchk) ^ lswz) << 4);
#pragma unroll
            for (int bi = 0; bi < 4; bi++) {
                uint32_t vh[4], vl[4];
                LDSM_X4(vh[0], vh[1], vh[2], vh[3], stb + 16384 + bRow[bi] + sw);
                LDSM_X4(vl[0], vl[1], vl[2], vl[3], stb + 24576 + bRow[bi] + sw);
                HMMA(o[2*bi],   phi, vh[0], vh[2]);
                HMMA(o[2*bi+1], phi, vh[1], vh[3]);
                HMMA(o[2*bi],   plo, vh[0], vh[2]);
                HMMA(o[2*bi+1], plo, vh[1], vh[3]);
                HMMA(o[2*bi],   phi, vl[0], vl[2]);
                HMMA(o[2*bi+1], phi, vl[1], vl[3]);
            }
        }
        __syncthreads();
    }

    // write ctx as bf16 hi/lo planes: row layout [hi 1024 | lo 1024]
    float inv0 = 1.0f / l0, inv1 = 1.0f / l1;
    int r = wid * 16 + (lane >> 2);
    long row0 = ((long)b * SEQ + q0 + r) * (2 * HID);
    long row1 = ((long)b * SEQ + q0 + r + 8) * (2 * HID);
#pragma unroll
    for (int nt = 0; nt < 8; nt++) {
        int col = h * DH + nt * 8 + (lane & 3) * 2;
        float v0 = o[nt][0] * inv0, v1 = o[nt][1] * inv0;
        float v2 = o[nt][2] * inv1, v3 = o[nt][3] * inv1;
        __nv_bfloat162 h0 = __floats2bfloat162_rn(v0, v1);
        __nv_bfloat162 h1 = __floats2bfloat162_rn(v2, v3);
        *(__nv_bfloat162*)&g_ctxbf[row0 + col] = h0;
        *(__nv_bfloat162*)&g_ctxbf[row1 + col] = h1;
        __nv_bfloat162 l0v = __floats2bfloat162_rn(v0 - __bfloat162float(h0.x),
                                                   v1 - __bfloat162float(h0.y));
        __nv_bfloat162 l1v = __floats2bfloat162_rn(v2 - __bfloat162float(h1.x),
                                                   v3 - __bfloat162float(h1.y));
        *(__nv_bfloat162*)&g_ctxbf[row0 + HID + col] = l0v;
        *(__nv_bfloat162*)&g_ctxbf[row1 + HID + col] = l1v;
    }
}

// ---------------- host launcher ---------------------------------------------
extern "C" void kernel_launch(void* const* d_in, const int* in_sizes, int n_in,
                              void* d_out, int out_size)
{
    const float* x   = (const float*)d_in[0];
    const float* bw  = (const float*)d_in[1];
    const float* sw  = (const float*)d_in[2];
    const float* sc  = (const float*)d_in[3];
    const float* grd = (const float*)d_in[4];
    const float* R   = (const float*)d_in[5];
    const float* ow  = (const float*)d_in[6];
    const float* ob  = (const float*)d_in[7];
    float* out = (float*)d_out;

    __nv_bfloat16 *pA, *pB, *pctx, *pow;
    float* pqkv;
    cudaGetSymbolAddress((void**)&pA,   g_Abf);
    cudaGetSymbolAddress((void**)&pB,   g_Bbf);
    cudaGetSymbolAddress((void**)&pqkv, g_qkv);
    cudaGetSymbolAddress((void**)&pctx, g_ctxbf);
    cudaGetSymbolAddress((void**)&pow,  g_owbf);

    cudaFuncSetAttribute(gemm3_mma, cudaFuncAttributeMaxDynamicSharedMemorySize,
                         NSTG * STG_BYTES);
    cudaFuncSetAttribute(flash_attn_mma, cudaFuncAttributeMaxDynamicSharedMemorySize,
                         FS_TOT);

    // 1-2. prep (bf16 hi/lo dedup storage)
    prep_w<<<(OUT3 * HID) / 256, 256>>>(bw, sw, sc);
    prep_a<<<(NTOK * HID) / 256, 256>>>(x, grd);
    prep_ow<<<(HID * HID) / 256, 256>>>(ow);
    // 3. fused KAN GEMM (virtual K = 27648)
    gemm3_mma<<<dim3(OUT3 / BN, NTOK / BM), 256, NSTG * STG_BYTES>>>(
        pA, pB, pqkv, K2, KDIM / BK, 3 * KDIM / BK, OUT3, nullptr);
    // 4. rotation -> bf16 q/8, k planes + v^T planes
    rotqkv<<<dim3(BHN, SEQ / 64), 256>>>(R);
    // 5. HMMA flash attention -> ctx (bf16 hi/lo planes)
    flash_attn_mma<<<dim3(SEQ / 64, BHN), 128, FS_TOT>>>();
    // 6. out-proj via 3-term HMMA (virtual K = 3072) + bias
    gemm3_mma<<<dim3(HID / BN, NTOK / BM), 256, NSTG * STG_BYTES>>>(
        pctx, pow, out, 2 * HID, HID / BK, 3 * HID / BK, HID, ob);
}

// round 11
// speedup vs baseline: 1.6504x; 1.6504x over previous
#include <cuda_runtime.h>
#include <cuda_bf16.h>
#include <math.h>
#include <stdint.h>

// Problem constants
#define HID   1024
#define NTOK  4096          // B*S
#define KDIM  9216          // 1024 silu + 8192 spline bases
#define K2    18432         // stored: [hi | lo]
#define OUT3  3072
#define SEQ   2048
#define BHN   32
#define DH    64

// GEMM tiling (CTA 256x128, K-chunk 128 = 2 planes of 64, 2-stage)
#define BM 256
#define BN 128
#define A_PL 32768          // one 64-col A plane (256 rows x 128B)
#define B_PL 16384          // one 64-col B plane (128 rows x 128B)
#define SM_B (2 * A_PL)     // 65536
#define STG_BYTES (2 * A_PL + 2 * B_PL)   // 98304
#define NSTG 2

// ---------------- scratch (static __device__, no allocations) ----------------
__device__ __align__(16) __nv_bfloat16 g_Abf[(long)NTOK * K2];   // 151 MB
__device__ __align__(16) __nv_bfloat16 g_Bbf[(long)OUT3 * K2];   // 113 MB
__device__ __align__(16) float g_qkv [(long)NTOK * OUT3];
__device__ __align__(16) __nv_bfloat16 g_qbf[(long)BHN * 2 * SEQ * DH];
__device__ __align__(16) __nv_bfloat16 g_kbf[(long)BHN * 2 * SEQ * DH];
__device__ __align__(16) __nv_bfloat16 g_vt [(long)BHN * 2 * DH * SEQ];
__device__ __align__(16) __nv_bfloat16 g_ctxbf[(long)NTOK * 2 * HID];  // [hi|lo]
__device__ __align__(16) __nv_bfloat16 g_owbf [(long)HID * 2 * HID];   // [hi|lo]

__device__ __forceinline__ uint32_t smem_u32(const void* p) {
    uint32_t a;
    asm("{ .reg .u64 t; cvta.to.shared.u64 t, %1; cvt.u32.u64 %0, t; }"
        : "=r"(a) : "l"(p));
    return a;
}
#define CP_ASYNC16(smaddr, gptr) \
    asm volatile("cp.async.cg.shared.global [%0], [%1], 16;" :: "r"(smaddr), "l"(gptr))
#define CP_COMMIT() asm volatile("cp.async.commit_group;")
#define CP_WAIT1()  asm volatile("cp.async.wait_group 1;")
#define CP_WAIT0()  asm volatile("cp.async.wait_group 0;")
#define LDSM_X4(r0,r1,r2,r3,addr) \
    asm volatile("ldmatrix.sync.aligned.m8n8.x4.shared.b16 {%0,%1,%2,%3}, [%4];" \
        : "=r"(r0),"=r"(r1),"=r"(r2),"=r"(r3) : "r"(addr))
#define HMMA(d, a, b0v, b1v) \
    asm volatile("mma.sync.aligned.m16n8k16.row.col.f32.bf16.bf16.f32 " \
        "{%0,%1,%2,%3}, {%4,%5,%6,%7}, {%8,%9}, {%0,%1,%2,%3};" \
        : "+f"(d[0]),"+f"(d[1]),"+f"(d[2]),"+f"(d[3]) \
        : "r"(a[0]),"r"(a[1]),"r"(a[2]),"r"(a[3]), "r"(b0v),"r"(b1v))

__device__ __forceinline__ uint32_t pk2(float a, float b) {
    __nv_bfloat162 t = __floats2bfloat162_rn(a, b);
    return *(uint32_t*)&t;
}

// ---------------- prep: Bbf = [hi | lo] of [bw | sw*sc] ----------------------
__global__ void prep_w(const float* __restrict__ bw,
                       const float* __restrict__ sw,
                       const float* __restrict__ sc)
{
    long i = (long)blockIdx.x * 256 + threadIdx.x;
    if (i >= (long)OUT3 * HID) return;
    int in = (int)(i & 1023);
    float s = sc[i];
    long rb = (long)(i >> 10) * K2;
    float v = bw[i];
    __nv_bfloat16 h = __float2bfloat16_rn(v);
    __nv_bfloat16 l = __float2bfloat16_rn(v - __bfloat162float(h));
    g_Bbf[rb + in] = h;
    g_Bbf[rb + KDIM + in] = l;
    __nv_bfloat16 h8[8], l8[8];
#pragma unroll
    for (int j = 0; j < 8; j++) {
        float w = sw[i * 8 + j] * s;
        h8[j] = __float2bfloat16_rn(w);
        l8[j] = __float2bfloat16_rn(w - __bfloat162float(h8[j]));
    }
    long c = rb + HID + (long)in * 8;
    *(uint4*)&g_Bbf[c]        = *(uint4*)h8;
    *(uint4*)&g_Bbf[c + KDIM] = *(uint4*)l8;
}

// ---------------- prep: Abf = [hi | lo] of [silu(x) | b_splines(x)] ---------
__global__ void prep_a(const float* __restrict__ x,
                       const float* __restrict__ grid)
{
    long i = (long)blockIdx.x * 256 + threadIdx.x;
    if (i >= (long)NTOK * HID) return;
    int in = (int)(i & 1023);
    float xv = x[i];
    long ra = (long)(i >> 10) * K2;
    float sv = xv / (1.0f + expf(-xv));
    __nv_bfloat16 h = __float2bfloat16_rn(sv);
    __nv_bfloat16 l = __float2bfloat16_rn(sv - __bfloat162float(h));
    g_Abf[ra + in] = h;
    g_Abf[ra + KDIM + in] = l;
    float g[12];
#pragma unroll
    for (int t = 0; t < 12; t++) g[t] = grid[in * 12 + t];
    float bas[11];
#pragma unroll
    for (int j = 0; j < 11; j++)
        bas[j] = (xv >= g[j] && xv < g[j + 1]) ? 1.0f : 0.0f;
#pragma unroll
    for (int p = 1; p <= 3; p++) {
#pragma unroll
        for (int j = 0; j < 11 - p; j++) {
            bas[j] = (xv - g[j]) / (g[j + p] - g[j]) * bas[j]
                   + (g[j + p + 1] - xv) / (g[j + p + 1] - g[j + 1]) * bas[j + 1];
        }
    }
    __nv_bfloat16 h8[8], l8[8];
#pragma unroll
    for (int j = 0; j < 8; j++) {
        h8[j] = __float2bfloat16_rn(bas[j]);
        l8[j] = __float2bfloat16_rn(bas[j] - __bfloat162float(h8[j]));
    }
    long c = ra + HID + (long)in * 8;
    *(uint4*)&g_Abf[c]        = *(uint4*)h8;
    *(uint4*)&g_Abf[c + KDIM] = *(uint4*)l8;
}

// ---------------- prep: out_w -> [hi | lo] -----------------------------------
__global__ void prep_ow(const float* __restrict__ ow)
{
    long i = (long)blockIdx.x * 256 + threadIdx.x;
    if (i >= (long)HID * HID) return;
    int c = (int)(i & 1023);
    long rb = (long)(i >> 10) * (2 * HID);
    float v = ow[i];
    __nv_bfloat16 h = __float2bfloat16_rn(v);
    __nv_bfloat16 l = __float2bfloat16_rn(v - __bfloat162float(h));
    g_owbf[rb + c] = h;
    g_owbf[rb + HID + c] = l;
}

// ---------------- generic 3-term split HMMA GEMM -----------------------------
// C(MxN) = A * B^T over virtual K = 3*kdim (A: hi,lo,hi / B: hi,hi,lo).
// CTA 256x128, K-tile 128 (2 planes of 64), 2-stage cp.async.
// seg = kdim/128, ntt = 3*kdim/128, k2 = 2*kdim.
__global__ void __launch_bounds__(256, 1) gemm3_mma(
    const __nv_bfloat16* __restrict__ A, const __nv_bfloat16* __restrict__ B,
    float* __restrict__ C,
    int k2, int seg, int ntt, int ldc, const float* __restrict__ bias)
{
    extern __shared__ char smem[];
    const uint32_t sb = smem_u32(smem);
    const int tid = threadIdx.x;
    const int wid = tid >> 5;
    const int lane = tid & 31;
    const int m0 = blockIdx.y * BM;
    const int n0 = blockIdx.x * BN;
    const int wm = wid & 3;
    const int wn = wid >> 2;

    const int r0 = tid >> 3;
    const int c0 = tid & 7;
    const __nv_bfloat16* aG = A + (long)(m0 + r0) * k2 + c0 * 8;
    const __nv_bfloat16* bG = B + (long)(n0 + r0) * k2 + c0 * 8;
    uint32_t sA[8], sB[4];
#pragma unroll
    for (int u = 0; u < 8; u++) {
        int row = r0 + u * 32;
        sA[u] = sb + row * 128 + ((c0 ^ (row & 7)) << 4);
    }
#pragma unroll
    for (int u = 0; u < 4; u++) {
        int row = r0 + u * 32;
        sB[u] = sb + SM_B + row * 128 + ((c0 ^ (row & 7)) << 4);
    }

    // preload k-tile 0 (both planes; chA=chB=0)
#pragma unroll
    for (int p = 0; p < 2; p++) {
        long co = (long)p * 64;
#pragma unroll
        for (int u = 0; u < 8; u++)
            CP_ASYNC16(sA[u] + p * A_PL, aG + (long)u * 32 * k2 + co);
#pragma unroll
        for (int u = 0; u < 4; u++)
            CP_ASYNC16(sB[u] + p * B_PL, bG + (long)u * 32 * k2 + co);
    }
    CP_COMMIT();

    float acc[4][8][4];
#pragma unroll
    for (int mi = 0; mi < 4; mi++)
#pragma unroll
        for (int ni = 0; ni < 8; ni++)
#pragma unroll
            for (int r = 0; r < 4; r++) acc[mi][ni][r] = 0.0f;

    const int lrow = lane & 15;
    const int lchk = lane >> 4;
    const int lswz = lane & 7;
    uint32_t aRow[4], bRow[4];
#pragma unroll
    for (int mi = 0; mi < 4; mi++)
        aRow[mi] = (uint32_t)((wm * 64 + mi * 16 + lrow) * 128);
#pragma unroll
    for (int bi = 0; bi < 4; bi++)
        bRow[bi] = (uint32_t)(SM_B + (wn * 64 + bi * 16 + lrow) * 128);

    for (int t = 0; t < ntt; t++) {
        CP_WAIT0();
        __syncthreads();
        // prefetch k-tile t+1 into the other buffer (overlaps compute of t)
        if (t + 1 < ntt) {
            int ch = t + 1;
            int chA = (ch < 2 * seg) ? ch : ch - 2 * seg;   // hi,lo,hi
            int chB = (ch < seg)     ? ch : ch - seg;       // hi,hi,lo
            uint32_t bo = ((t + 1) & 1) * STG_BYTES;
#pragma unroll
            for (int p = 0; p < 2; p++) {
                long coA = (long)chA * 128 + p * 64;
                long coB = (long)chB * 128 + p * 64;
#pragma unroll
                for (int u = 0; u < 8; u++)
                    CP_ASYNC16(sA[u] + bo + p * A_PL, aG + (long)u * 32 * k2 + coA);
#pragma unroll
                for (int u = 0; u < 4; u++)
                    CP_ASYNC16(sB[u] + bo + p * B_PL, bG + (long)u * 32 * k2 + coB);
            }
            CP_COMMIT();
        }

        const uint32_t stb = sb + (t & 1) * STG_BYTES;
#pragma unroll
        for (int kk = 0; kk < 8; kk++) {
            const int pl = kk >> 2;
            const uint32_t chq = (uint32_t)((kk & 3) * 2 + lchk);
            const uint32_t sw = (chq ^ (uint32_t)lswz) << 4;
            uint32_t a[4][4], b[4][4];
#pragma unroll
            for (int mi = 0; mi < 4; mi++) {
                uint32_t ad = stb + pl * A_PL + aRow[mi] + sw;
                LDSM_X4(a[mi][0], a[mi][1], a[mi][2], a[mi][3], ad);
            }
#pragma unroll
            for (int bi = 0; bi < 4; bi++) {
                uint32_t bd = stb + pl * B_PL + bRow[bi] + sw;
                LDSM_X4(b[bi][0], b[bi][1], b[bi][2], b[bi][3], bd);
            }
#pragma unroll
            for (int mi = 0; mi < 4; mi++)
#pragma unroll
                for (int bi = 0; bi < 4; bi++) {
                    HMMA(acc[mi][2*bi],   a[mi], b[bi][0], b[bi][2]);
                    HMMA(acc[mi][2*bi+1], a[mi], b[bi][1], b[bi][3]);
                }
        }
    }

    const int erow = lane >> 2;
    const int ecol = (lane & 3) * 2;
#pragma unroll
    for (int mi = 0; mi < 4; mi++) {
        long row = m0 + wm * 64 + mi * 16 + erow;
#pragma unroll
        for (int ni = 0; ni < 8; ni++) {
            int col = n0 + wn * 64 + ni * 8 + ecol;
            float v0 = acc[mi][ni][0], v1 = acc[mi][ni][1];
            float v2 = acc[mi][ni][2], v3 = acc[mi][ni][3];
            if (bias) {
                float b0 = bias[col], b1 = bias[col + 1];
                v0 += b0; v1 += b1; v2 += b0; v3 += b1;
            }
            *(float2*)&C[row * ldc + col] = make_float2(v0, v1);
            *(float2*)&C[(row + 8) * ldc + col] = make_float2(v2, v3);
        }
    }
}

// ---------------- rotate q,k by R; emit bf16 hi/lo planes + v^T -------------
__global__ void __launch_bounds__(256) rotqkv(const float* __restrict__ R)
{
    const int bh = blockIdx.x;
    const int s0 = blockIdx.y * 64;
    const int b = bh >> 4, h = bh & 15;
    __shared__ float RsT[64][65];
    __shared__ float T[64][65];
    __shared__ float Tv[64][65];
    const int tid = threadIdx.x;
    const long plane = (long)SEQ * DH;
    const long vplane = (long)DH * SEQ;

    for (int i = tid; i < 4096; i += 256) {
        int m = i >> 6, d = i & 63;
        RsT[d][m] = R[i];
    }
    for (int i = tid; i < 4096; i += 256) {
        int t = i >> 6, d = i & 63;
        long n = (long)(b * SEQ + s0 + t);
        const float* base = g_qkv + n * OUT3 + h * 192;
        T[t][d] = base[d];
        Tv[t][d] = base[128 + d];
    }
    __syncthreads();
    for (int i = tid; i < 4096; i += 256) {
        int t = i >> 6, m = i & 63;
        float sum = 0.0f;
#pragma unroll
        for (int d = 0; d < 64; d++) sum += T[t][d] * RsT[d][m];
        sum *= 0.125f;
        __nv_bfloat16 hi = __float2bfloat16_rn(sum);
        __nv_bfloat16 lo = __float2bfloat16_rn(sum - __bfloat162float(hi));
        long idx = ((long)(bh * 2) * SEQ + s0 + t) * DH + m;
        g_qbf[idx] = hi;
        g_qbf[idx + plane] = lo;
    }
    for (int i = tid; i < 4096; i += 256) {
        int d = i >> 6, t = i & 63;
        float v = Tv[t][d];
        __nv_bfloat16 hi = __float2bfloat16_rn(v);
        __nv_bfloat16 lo = __float2bfloat16_rn(v - __bfloat162float(hi));
        long idx = ((long)(bh * 2) * DH + d) * SEQ + s0 + t;
        g_vt[idx] = hi;
        g_vt[idx + vplane] = lo;
    }
    __syncthreads();
    for (int i = tid; i < 4096; i += 256) {
        int t = i >> 6, d = i & 63;
        long n = (long)(b * SEQ + s0 + t);
        T[t][d] = g_qkv[n * OUT3 + h * 192 + 64 + d];
    }
    __syncthreads();
    for (int i = tid; i < 4096; i += 256) {
        int t = i >> 6, m = i & 63;
        float sum = 0.0f;
#pragma unroll
        for (int d = 0; d < 64; d++) sum += T[t][d] * RsT[d][m];
        __nv_bfloat16 hi = __float2bfloat16_rn(sum);
        __nv_bfloat16 lo = __float2bfloat16_rn(sum - __bfloat162float(hi));
        long idx = ((long)(bh * 2) * SEQ + s0 + t) * DH + m;
        g_kbf[idx] = hi;
        g_kbf[idx + plane] = lo;
    }
}

// ---------------- HMMA flash attention; ctx out as bf16 hi/lo ---------------
#define FS_KV   16384
#define FS_BUF  32768
#define FS_TOT  (FS_KV + 2 * FS_BUF)
__global__ void __launch_bounds__(128, 1) flash_attn_mma()
{
    extern __shared__ char smem[];
    const uint32_t sb = smem_u32(smem);
    const int tid = threadIdx.x;
    const int wid = tid >> 5;
    const int lane = tid & 31;
    const int bh = blockIdx.y;
    const int q0 = blockIdx.x * 64;
    const int b = bh >> 4, h = bh & 15;

    const int lr = tid >> 3;
    const int lc = tid & 7;
    uint32_t soff[4];
#pragma unroll
    for (int u = 0; u < 4; u++) {
        int row = lr + u * 16;
        soff[u] = row * 128 + ((lc ^ (row & 7)) << 4);
    }
    const long qplane = (long)SEQ * DH;
    const long vplane = (long)DH * SEQ;

#pragma unroll
    for (int p = 0; p < 2; p++)
#pragma unroll
        for (int u = 0; u < 4; u++) {
            int row = lr + u * 16;
            const __nv_bfloat16* src =
                g_qbf + ((long)(bh * 2) * SEQ + q0 + row) * DH + p * qplane + lc * 8;
            CP_ASYNC16(sb + p * 8192 + soff[u], src);
        }
    {
        uint32_t bo = sb + FS_KV;
#pragma unroll
        for (int p = 0; p < 2; p++)
#pragma unroll
            for (int u = 0; u < 4; u++) {
                int row = lr + u * 16;
                const __nv_bfloat16* ks =
                    g_kbf + ((long)(bh * 2) * SEQ + row) * DH + p * qplane + lc * 8;
                CP_ASYNC16(bo + p * 8192 + soff[u], ks);
                const __nv_bfloat16* vs =
                    g_vt + ((long)(bh * 2) * DH + row) * SEQ + p * vplane + lc * 8;
                CP_ASYNC16(bo + 16384 + p * 8192 + soff[u], vs);
            }
    }
    CP_COMMIT();

    const int lrow = lane & 15;
    const int lchk = lane >> 4;
    const int lswz = lane & 7;
    const uint32_t aRow = (uint32_t)((wid * 16 + lrow) * 128);
    uint32_t bRow[4];
#pragma unroll
    for (int bi = 0; bi < 4; bi++)
        bRow[bi] = (uint32_t)((bi * 16 + lrow) * 128);

    float m0 = -1e30f, m1 = -1e30f, l0 = 0.f, l1 = 0.f;
    float o[8][4];
#pragma unroll
    for (int nt = 0; nt < 8; nt++)
#pragma unroll
        for (int r = 0; r < 4; r++) o[nt][r] = 0.0f;

    const int NKT = SEQ / 64;
    for (int t = 0; t < NKT; t++) {
        if (t + 1 < NKT) {
            uint32_t bo = sb + FS_KV + ((t + 1) & 1) * FS_BUF;
            int s0n = (t + 1) * 64;
#pragma unroll
            for (int p = 0; p < 2; p++)
#pragma unroll
                for (int u = 0; u < 4; u++) {
                    int row = lr + u * 16;
                    const __nv_bfloat16* ks =
                        g_kbf + ((long)(bh * 2) * SEQ + s0n + row) * DH + p * qplane + lc * 8;
                    CP_ASYNC16(bo + p * 8192 + soff[u], ks);
                    const __nv_bfloat16* vs =
                        g_vt + ((long)(bh * 2) * DH + row) * SEQ + p * vplane + s0n + lc * 8;
                    CP_ASYNC16(bo + 16384 + p * 8192 + soff[u], vs);
                }
            CP_COMMIT();
            CP_WAIT1();
        } else {
            CP_WAIT0();
        }
        __syncthreads();

        const uint32_t stb = sb + FS_KV + (t & 1) * FS_BUF;

        float s[8][4];
#pragma unroll
        for (int nt = 0; nt < 8; nt++)
#pragma unroll
            for (int r = 0; r < 4; r++) s[nt][r] = 0.0f;
#pragma unroll
        for (int kk = 0; kk < 4; kk++) {
            const uint32_t sw = (uint32_t)(((kk * 2 + lchk) ^ lswz) << 4);
            uint32_t ah[4], al[4];
            LDSM_X4(ah[0], ah[1], ah[2], ah[3], sb + aRow + sw);
            LDSM_X4(al[0], al[1], al[2], al[3], sb + 8192 + aRow + sw);
#pragma unroll
            for (int bi = 0; bi < 4; bi++) {
                uint32_t kh[4], kl[4];
                LDSM_X4(kh[0], kh[1], kh[2], kh[3], stb + bRow[bi] + sw);
                LDSM_X4(kl[0], kl[1], kl[2], kl[3], stb + 8192 + bRow[bi] + sw);
                HMMA(s[2*bi],   ah, kh[0], kh[2]);
                HMMA(s[2*bi+1], ah, kh[1], kh[3]);
                HMMA(s[2*bi],   al, kh[0], kh[2]);
                HMMA(s[2*bi+1], al, kh[1], kh[3]);
                HMMA(s[2*bi],   ah, kl[0], kl[2]);
                HMMA(s[2*bi+1], ah, kl[1], kl[3]);
            }
        }

        float tm0 = -1e30f, tm1 = -1e30f;
#pragma unroll
        for (int nt = 0; nt < 8; nt++) {
            tm0 = fmaxf(tm0, fmaxf(s[nt][0], s[nt][1]));
            tm1 = fmaxf(tm1, fmaxf(s[nt][2], s[nt][3]));
        }
        tm0 = fmaxf(tm0, __shfl_xor_sync(0xffffffffu, tm0, 1));
        tm0 = fmaxf(tm0, __shfl_xor_sync(0xffffffffu, tm0, 2));
        tm1 = fmaxf(tm1, __shfl_xor_sync(0xffffffffu, tm1, 1));
        tm1 = fmaxf(tm1, __shfl_xor_sync(0xffffffffu, tm1, 2));
        float nm0 = fmaxf(m0, tm0), nm1 = fmaxf(m1, tm1);
        float c0 = __expf(m0 - nm0), c1 = __expf(m1 - nm1);
        m0 = nm0; m1 = nm1;
        float p[8][4];
        float ts0 = 0.f, ts1 = 0.f;
#pragma unroll
        for (int nt = 0; nt < 8; nt++) {
            p[nt][0] = __expf(s[nt][0] - nm0);
            p[nt][1] = __expf(s[nt][1] - nm0);
            p[nt][2] = __expf(s[nt][2] - nm1);
            p[nt][3] = __expf(s[nt][3] - nm1);
            ts0 += p[nt][0] + p[nt][1];
            ts1 += p[nt][2] + p[nt][3];
        }
        ts0 += __shfl_xor_sync(0xffffffffu, ts0, 1);
        ts0 += __shfl_xor_sync(0xffffffffu, ts0, 2);
        ts1 += __shfl_xor_sync(0xffffffffu, ts1, 1);
        ts1 += __shfl_xor_sync(0xffffffffu, ts1, 2);
        l0 = l0 * c0 + ts0;
        l1 = l1 * c1 + ts1;
#pragma unroll
        for (int nt = 0; nt < 8; nt++) {
            o[nt][0] *= c0; o[nt][1] *= c0;
            o[nt][2] *= c1; o[nt][3] *= c1;
        }

#pragma unroll
        for (int kb = 0; kb < 4; kb++) {
            float h00 = p[2*kb][0], h01 = p[2*kb][1];
            float h02 = p[2*kb][2], h03 = p[2*kb][3];
            float h10 = p[2*kb+1][0], h11 = p[2*kb+1][1];
            float h12 = p[2*kb+1][2], h13 = p[2*kb+1][3];
            uint32_t phi[4], plo[4];
            phi[0] = pk2(h00, h01); phi[1] = pk2(h02, h03);
            phi[2] = pk2(h10, h11); phi[3] = pk2(h12, h13);
            __nv_bfloat162 t0 = *(__nv_bfloat162*)&phi[0];
            __nv_bfloat162 t1 = *(__nv_bfloat162*)&phi[1];
            __nv_bfloat162 t2 = *(__nv_bfloat162*)&phi[2];
            __nv_bfloat162 t3 = *(__nv_bfloat162*)&phi[3];
            plo[0] = pk2(h00 - __bfloat162float(t0.x), h01 - __bfloat162float(t0.y));
            plo[1] = pk2(h02 - __bfloat162float(t1.x), h03 - __bfloat162float(t1.y));
            plo[2] = pk2(h10 - __bfloat162float(t2.x), h11 - __bfloat162float(t2.y));
            plo[3] = pk2(h12 - __bfloat162float(t3.x), h13 - __bfloat162float(t3.y));

            const uint32_t sw = (uint32_t)(((kb * 2 + lchk) ^ lswz) << 4);
#pragma unroll
            for (int bi = 0; bi < 4; bi++) {
                uint32_t vh[4], vl[4];
                LDSM_X4(vh[0], vh[1], vh[2], vh[3], stb + 16384 + bRow[bi] + sw);
                LDSM_X4(vl[0], vl[1], vl[2], vl[3], stb + 24576 + bRow[bi] + sw);
                HMMA(o[2*bi],   phi, vh[0], vh[2]);
                HMMA(o[2*bi+1], phi, vh[1], vh[3]);
                HMMA(o[2*bi],   plo, vh[0], vh[2]);
                HMMA(o[2*bi+1], plo, vh[1], vh[3]);
                HMMA(o[2*bi],   phi, vl[0], vl[2]);
                HMMA(o[2*bi+1], phi, vl[1], vl[3]);
            }
        }
        __syncthreads();
    }

    // write ctx as bf16 hi/lo planes: row layout [hi 1024 | lo 1024]
    float inv0 = 1.0f / l0, inv1 = 1.0f / l1;
    int r = wid * 16 + (lane >> 2);
    long row0 = ((long)b * SEQ + q0 + r) * (2 * HID);
    long row1 = ((long)b * SEQ + q0 + r + 8) * (2 * HID);
#pragma unroll
    for (int nt = 0; nt < 8; nt++) {
        int col = h * DH + nt * 8 + (lane & 3) * 2;
        float v0 = o[nt][0] * inv0, v1 = o[nt][1] * inv0;
        float v2 = o[nt][2] * inv1, v3 = o[nt][3] * inv1;
        __nv_bfloat162 h0 = __floats2bfloat162_rn(v0, v1);
        __nv_bfloat162 h1 = __floats2bfloat162_rn(v2, v3);
        *(__nv_bfloat162*)&g_ctxbf[row0 + col] = h0;
        *(__nv_bfloat162*)&g_ctxbf[row1 + col] = h1;
        __nv_bfloat162 l0v = __floats2bfloat162_rn(v0 - __bfloat162float(h0.x),
                                                   v1 - __bfloat162float(h0.y));
        __nv_bfloat162 l1v = __floats2bfloat162_rn(v2 - __bfloat162float(h1.x),
                                                   v3 - __bfloat162float(h1.y));
        *(__nv_bfloat162*)&g_ctxbf[row0 + HID + col] = l0v;
        *(__nv_bfloat162*)&g_ctxbf[row1 + HID + col] = l1v;
    }
}

// ---------------- host launcher ---------------------------------------------
extern "C" void kernel_launch(void* const* d_in, const int* in_sizes, int n_in,
                              void* d_out, int out_size)
{
    const float* x   = (const float*)d_in[0];
    const float* bw  = (const float*)d_in[1];
    const float* sw  = (const float*)d_in[2];
    const float* sc  = (const float*)d_in[3];
    const float* grd = (const float*)d_in[4];
    const float* R   = (const float*)d_in[5];
    const float* ow  = (const float*)d_in[6];
    const float* ob  = (const float*)d_in[7];
    float* out = (float*)d_out;

    __nv_bfloat16 *pA, *pB, *pctx, *pow;
    float* pqkv;
    cudaGetSymbolAddress((void**)&pA,   g_Abf);
    cudaGetSymbolAddress((void**)&pB,   g_Bbf);
    cudaGetSymbolAddress((void**)&pqkv, g_qkv);
    cudaGetSymbolAddress((void**)&pctx, g_ctxbf);
    cudaGetSymbolAddress((void**)&pow,  g_owbf);

    cudaFuncSetAttribute(gemm3_mma, cudaFuncAttributeMaxDynamicSharedMemorySize,
                         NSTG * STG_BYTES);
    cudaFuncSetAttribute(flash_attn_mma, cudaFuncAttributeMaxDynamicSharedMemorySize,
                         FS_TOT);

    // 1-2. prep (bf16 hi/lo dedup storage)
    prep_w<<<(OUT3 * HID) / 256, 256>>>(bw, sw, sc);
    prep_a<<<(NTOK * HID) / 256, 256>>>(x, grd);
    prep_ow<<<(HID * HID) / 256, 256>>>(ow);
    // 3. fused KAN GEMM (virtual K = 27648, K-tile 128)
    gemm3_mma<<<dim3(OUT3 / BN, NTOK / BM), 256, NSTG * STG_BYTES>>>(
        pA, pB, pqkv, K2, KDIM / 128, 3 * KDIM / 128, OUT3, nullptr);
    // 4. rotation -> bf16 q/8, k planes + v^T planes
    rotqkv<<<dim3(BHN, SEQ / 64), 256>>>(R);
    // 5. HMMA flash attention -> ctx (bf16 hi/lo planes)
    flash_attn_mma<<<dim3(SEQ / 64, BHN), 128, FS_TOT>>>();
    // 6. out-proj via 3-term HMMA (virtual K = 3072, K-tile 128) + bias
    gemm3_mma<<<dim3(HID / BN, NTOK / BM), 256, NSTG * STG_BYTES>>>(
        pctx, pow, out, 2 * HID, HID / 128, 3 * HID / 128, HID, ob);
}